// round 9
// baseline (speedup 1.0000x reference)
#include <cuda_runtime.h>
#include <cuda_bf16.h>
#include <cstdint>

// ---------------------------------------------------------------------------
// LinearAttention (Taylor 2nd-order feature map), b=1, l=1024, dm=1024,
// 16 heads, feature_dim=16, head_dim=64.  D = 1+16+256 = 273 features.
//
//   S:    split hs/W1/Wo to K-concat split-bf16 (K=3072)
//   G1:   qkv = hs2 @ W1^T             (mma.sync bf16, 4-stage cp.async)
//   PHIQ: phi(q) -> split-bf16 A rows  [h][l][896]  ([hi|hi|lo], pads=0)
//   K2:   per (h,c): KV_c = phi(k)^T V, Kz_c  (fp32 SIMT, f32x2)
//   ST:   per (h,c): S = prefix(KV) -> split-bf16 B rows [64][896]; z prefix
//   SC:   per (h,c): masked scores -> split A [128][384]; V^T -> split B
//         [64][384]; exact fp32 den -> g_den
//   A2:   per (h,c): HMMA GEMM K=1280 (inter 896 + intra 384), divide by den,
//         write split-bf16 y2
//   G2:   out = y2 @ Wo2^T
// ---------------------------------------------------------------------------

#define LSEQ   1024
#define NH     16
#define CHUNK  128
#define NCHUNK 8
#define DFEAT  273
#define DP2    280
#define PHI_C1 0.5f
#define PHI_C2 0.17677669529663687f
#define EPSV   1e-12f
#define KSPLIT 3072
#define NSTAGE 48
#define ROWB   144                      // smem row pitch for 64-col bf16 tiles
#define KPQ    896                      // phiq / st row length (3*288 + 32 pad)
#define KIN    384                      // score / vt row length (3*128)

// Scratch (static device globals; no allocation allowed)
__device__ __align__(16) float g_qkv[LSEQ * 1536];
__device__ __align__(16) float g_kv[NH * NCHUNK * DP2 * 64];
__device__ __align__(16) float g_kz[NH * NCHUNK * DP2];
__device__ __align__(16) float g_z  [NH * NCHUNK * 288];
__device__ __align__(16) float g_den[NH * NCHUNK * 128];
__device__ __align__(16) __nv_bfloat16 g_hs2[LSEQ * KSPLIT];
__device__ __align__(16) __nv_bfloat16 g_w1 [1536 * KSPLIT];
__device__ __align__(16) __nv_bfloat16 g_y2 [LSEQ * KSPLIT];
__device__ __align__(16) __nv_bfloat16 g_wo2[1024 * KSPLIT];
__device__ __align__(16) __nv_bfloat16 g_phiq [NH * LSEQ * KPQ];
__device__ __align__(16) __nv_bfloat16 g_st   [NH * NCHUNK * 64 * KPQ];
__device__ __align__(16) __nv_bfloat16 g_score[NH * NCHUNK * 128 * KIN];
__device__ __align__(16) __nv_bfloat16 g_vt   [NH * NCHUNK * 64 * KIN];

// ---------------- packed f32x2 helpers (used by K2) -------------------------
__device__ __forceinline__ unsigned long long pk2(float lo, float hi) {
    unsigned long long r;
    asm("mov.b64 %0, {%1, %2};" : "=l"(r)
        : "r"(__float_as_uint(lo)), "r"(__float_as_uint(hi)));
    return r;
}
__device__ __forceinline__ void ffma2(unsigned long long& d,
                                      unsigned long long a,
                                      unsigned long long b) {
    asm("fma.rn.f32x2 %0, %1, %2, %0;" : "+l"(d) : "l"(a), "l"(b));
}
__device__ __forceinline__ void upk2(unsigned long long v, float& lo, float& hi) {
    uint32_t a, b;
    asm("mov.b64 {%0, %1}, %2;" : "=r"(a), "=r"(b) : "l"(v));
    lo = __uint_as_float(a); hi = __uint_as_float(b);
}

// ---------------- PTX helpers -----------------------------------------------
__device__ __forceinline__ uint32_t smem_u32(const void* p) {
    uint32_t a;
    asm("{ .reg .u64 t; cvta.to.shared.u64 t, %1; cvt.u32.u64 %0, t; }"
        : "=r"(a) : "l"(p));
    return a;
}
__device__ __forceinline__ void cp16(uint32_t saddr, const void* g) {
    asm volatile("cp.async.cg.shared.global [%0], [%1], 16;"
                 :: "r"(saddr), "l"(g) : "memory");
}
__device__ __forceinline__ void ldsm_x4(uint32_t& r0, uint32_t& r1,
                                        uint32_t& r2, uint32_t& r3,
                                        uint32_t addr) {
    asm volatile("ldmatrix.sync.aligned.m8n8.x4.shared.b16 {%0,%1,%2,%3}, [%4];"
                 : "=r"(r0), "=r"(r1), "=r"(r2), "=r"(r3) : "r"(addr));
}
__device__ __forceinline__ void mma16816(float* c, const uint32_t* a,
                                         const uint32_t* b) {
    asm volatile("mma.sync.aligned.m16n8k16.row.col.f32.bf16.bf16.f32 "
                 "{%0,%1,%2,%3}, {%4,%5,%6,%7}, {%8,%9}, {%0,%1,%2,%3};"
                 : "+f"(c[0]), "+f"(c[1]), "+f"(c[2]), "+f"(c[3])
                 : "r"(a[0]), "r"(a[1]), "r"(a[2]), "r"(a[3]),
                   "r"(b[0]), "r"(b[1]));
}

// ---------------- fused split kernel ----------------------------------------
__device__ __forceinline__ void split4(float4 x, __nv_bfloat162& h01,
                                       __nv_bfloat162& h23, __nv_bfloat162& l01,
                                       __nv_bfloat162& l23) {
    h01 = __floats2bfloat162_rn(x.x, x.y);
    h23 = __floats2bfloat162_rn(x.z, x.w);
    l01 = __floats2bfloat162_rn(x.x - __bfloat162float(h01.x),
                                x.y - __bfloat162float(h01.y));
    l23 = __floats2bfloat162_rn(x.z - __bfloat162float(h23.x),
                                x.w - __bfloat162float(h23.y));
}

__global__ __launch_bounds__(256) void split_all_kernel(
    const float* __restrict__ hs, const float* __restrict__ Wq,
    const float* __restrict__ Wk, const float* __restrict__ Wv,
    const float* __restrict__ Wo) {
    const int r = blockIdx.x, c = threadIdx.x * 4;
    const float* src;
    __nv_bfloat16* dst;
    bool alay;
    if (r < 1024) {
        src = hs + (size_t)r * 1024; dst = g_hs2 + (size_t)r * KSPLIT; alay = true;
    } else if (r < 2560) {
        int rr = r - 1024;
        const float* w; int wr;
        if (rr < 256)      { w = Wq; wr = rr; }
        else if (rr < 512) { w = Wk; wr = rr - 256; }
        else               { w = Wv; wr = rr - 512; }
        src = w + (size_t)wr * 1024; dst = g_w1 + (size_t)rr * KSPLIT; alay = false;
    } else {
        int rr = r - 2560;
        src = Wo + (size_t)rr * 1024; dst = g_wo2 + (size_t)rr * KSPLIT; alay = false;
    }
    float4 x = *(const float4*)&src[c];
    __nv_bfloat162 h01, h23, l01, l23;
    split4(x, h01, h23, l01, l23);
    __nv_bfloat162* d0 = (__nv_bfloat162*)&dst[c];
    __nv_bfloat162* d1 = (__nv_bfloat162*)&dst[1024 + c];
    __nv_bfloat162* d2 = (__nv_bfloat162*)&dst[2048 + c];
    d0[0] = h01; d0[1] = h23;
    if (alay) { d1[0] = h01; d1[1] = h23; d2[0] = l01; d2[1] = l23; }
    else      { d1[0] = l01; d1[1] = l23; d2[0] = h01; d2[1] = h23; }
}

// ---------------- mma.sync bf16 NT GEMM (projections) -----------------------
template <int NTILE>
__global__ __launch_bounds__(256) void mma_gemm_kernel(
    const __nv_bfloat16* __restrict__ A, const __nv_bfloat16* __restrict__ B,
    float* __restrict__ C, int ldc) {
    constexpr int WN   = NTILE / 4;
    constexpr int NT8  = WN / 8;
    constexpr int ROWS = 128 + NTILE;
    constexpr int SBYTES = ROWS * ROWB;

    extern __shared__ __align__(128) char sm[];
    const uint32_t sbase = smem_u32(sm);
    const int tid = threadIdx.x, lid = tid & 31, wid = tid >> 5;
    const int m0 = blockIdx.y * 128, n0 = blockIdx.x * NTILE;
    const int wm = wid & 1, wn = wid >> 1;

    auto load_stage = [&](int s, int buf) {
        const uint32_t base = sbase + buf * SBYTES;
#pragma unroll
        for (int i = 0; i < ROWS / 32; i++) {
            int idx = tid + i * 256;
            int row = idx >> 3, ch = idx & 7;
            const __nv_bfloat16* g =
                (row < 128)
                    ? A + (size_t)(m0 + row) * KSPLIT + s * 64 + ch * 8
                    : B + (size_t)(n0 + row - 128) * KSPLIT + s * 64 + ch * 8;
            cp16(base + row * ROWB + ch * 16, g);
        }
    };

    auto load_frags = [&](int buf, int k, uint32_t af[4][4],
                          uint32_t bfr[NT8][2]) {
        const uint32_t abase = sbase + buf * SBYTES +
            (wm * 64 + (lid & 15)) * ROWB + (lid >> 4) * 16 + k * 32;
#pragma unroll
        for (int mt = 0; mt < 4; mt++)
            ldsm_x4(af[mt][0], af[mt][1], af[mt][2], af[mt][3],
                    abase + mt * 16 * ROWB);
        const uint32_t bbase = sbase + buf * SBYTES + 128 * ROWB +
            (wn * WN + (lid & 15)) * ROWB + (lid >> 4) * 16 + k * 32;
#pragma unroll
        for (int nt2 = 0; nt2 < NT8 / 2; nt2++) {
            uint32_t r0, r1, r2, r3;
            ldsm_x4(r0, r1, r2, r3, bbase + nt2 * 16 * ROWB);
            bfr[2 * nt2][0] = r0; bfr[2 * nt2][1] = r2;
            bfr[2 * nt2 + 1][0] = r1; bfr[2 * nt2 + 1][1] = r3;
        }
    };

    float acc[4][NT8][4] = {};

    load_stage(0, 0); asm volatile("cp.async.commit_group;" ::: "memory");
    load_stage(1, 1); asm volatile("cp.async.commit_group;" ::: "memory");
    load_stage(2, 2); asm volatile("cp.async.commit_group;" ::: "memory");

    uint32_t af[2][4][4], bfr[2][NT8][2];

    for (int s = 0; s < NSTAGE; s++) {
        const int buf = s & 3;
        asm volatile("cp.async.wait_group 2;" ::: "memory");
        __syncthreads();
        load_frags(buf, 0, af[0], bfr[0]);
        if (s + 3 < NSTAGE) load_stage(s + 3, (s + 3) & 3);
        asm volatile("cp.async.commit_group;" ::: "memory");
#pragma unroll
        for (int k = 0; k < 4; k++) {
            if (k < 3) load_frags(buf, k + 1, af[(k + 1) & 1], bfr[(k + 1) & 1]);
#pragma unroll
            for (int mt = 0; mt < 4; mt++)
#pragma unroll
                for (int nt = 0; nt < NT8; nt++)
                    mma16816(acc[mt][nt], af[k & 1][mt], bfr[k & 1][nt]);
        }
    }

    const int r = lid >> 2, cq = (lid & 3) * 2;
#pragma unroll
    for (int mt = 0; mt < 4; mt++) {
        const int mrow = m0 + wm * 64 + mt * 16 + r;
#pragma unroll
        for (int nt = 0; nt < NT8; nt++) {
            const int col = n0 + wn * WN + nt * 8 + cq;
            *(float2*)&C[(size_t)mrow * ldc + col] =
                make_float2(acc[mt][nt][0], acc[mt][nt][1]);
            *(float2*)&C[(size_t)(mrow + 8) * ldc + col] =
                make_float2(acc[mt][nt][2], acc[mt][nt][3]);
        }
    }
}

// ---------------- phiq: phi(q) -> split-bf16 A rows [h][l][896] -------------
__global__ __launch_bounds__(256) void phiq_kernel() {
    __shared__ float qs[256];
    const int l = blockIdx.x, tid = threadIdx.x;
    qs[tid] = g_qkv[l * 1536 + tid];     // q for all 16 heads
    __syncthreads();
    for (int idx = tid; idx < NH * KPQ; idx += 256) {
        const int h = idx / KPQ;
        const int col = idx - h * KPQ;
        const float* qh = &qs[h * 16];
        int sec = (col >= 576) ? 2 : (col >= 288 ? 1 : 0);
        int cs = col - sec * 288;
        float v = 0.f;
        if (col < 864) {
            if (cs == 0)       v = 1.0f;
            else if (cs <= 16) v = qh[cs - 1] * PHI_C1;
            else if (cs < 273) {
                int e = cs - 17;
                v = qh[e >> 4] * qh[e & 15] * PHI_C2;
            }
        }
        __nv_bfloat16 hb = __float2bfloat16(v);
        __nv_bfloat16 ob = (sec == 2)
            ? __float2bfloat16(v - __bfloat162float(hb)) : hb;
        g_phiq[((size_t)h * LSEQ + l) * KPQ + col] = ob;
    }
}

// ---------------- K2: per-chunk KV / Kz sums (fp32 SIMT) --------------------
#define K2_SMEM ((128 * DP2 + 128 * 64 + 128 * 16) * 4)

__global__ __launch_bounds__(256) void chunk_kv_kernel() {
    extern __shared__ __align__(16) float sm2[];
    float* phik = sm2;
    float* vbuf = phik + 128 * DP2;
    float* kbuf = vbuf + 128 * 64;

    const int c = blockIdx.x, h = blockIdx.y;
    const int tid = threadIdx.x;
    const int rowbase = c * CHUNK;

    for (int i = tid; i < 512; i += 256) {
        int t = i >> 2, q4 = (i & 3) * 4;
        *(float4*)&kbuf[t * 16 + q4] =
            *(const float4*)&g_qkv[(rowbase + t) * 1536 + 256 + h * 16 + q4];
    }
    for (int i = tid; i < 2048; i += 256) {
        int t = i >> 4, q4 = (i & 15) * 4;
        *(float4*)&vbuf[t * 64 + q4] =
            *(const float4*)&g_qkv[(rowbase + t) * 1536 + 512 + h * 64 + q4];
    }
    __syncthreads();

    for (int idx = tid; idx < 128 * DP2; idx += 256) {
        int t = idx / DP2;
        int D = idx - t * DP2;
        float val;
        if (D == 0)        val = 1.0f;
        else if (D <= 16)  val = kbuf[t * 16 + (D - 1)] * PHI_C1;
        else if (D < DFEAT) {
            int e = D - 17;
            val = kbuf[t * 16 + (e >> 4)] * kbuf[t * 16 + (e & 15)] * PHI_C2;
        } else val = 0.0f;
        phik[idx] = val;
    }
    __syncthreads();

    float* KVout = g_kv + (h * NCHUNK + c) * DP2 * 64;
    for (int tile = tid; tile < 35 * 16; tile += 256) {
        const int d0 = (tile >> 4) * 8;
        const int j0 = (tile & 15) * 4;
        unsigned long long acc[4][4] = {};
        const float* pr = &phik[d0];
        const float* vr = &vbuf[j0];
#pragma unroll 2
        for (int t = 0; t < 128; t++) {
            ulonglong2 p01 = *(const ulonglong2*)(pr + t * DP2);
            ulonglong2 p23 = *(const ulonglong2*)(pr + t * DP2 + 4);
            float4 v = *(const float4*)(vr + t * 64);
            float vv[4] = {v.x, v.y, v.z, v.w};
#pragma unroll
            for (int j = 0; j < 4; j++) {
                unsigned long long vj = pk2(vv[j], vv[j]);
                ffma2(acc[j][0], vj, p01.x);
                ffma2(acc[j][1], vj, p01.y);
                ffma2(acc[j][2], vj, p23.x);
                ffma2(acc[j][3], vj, p23.y);
            }
        }
#pragma unroll
        for (int dp = 0; dp < 4; dp++) {
            float e0[4], e1[4];
#pragma unroll
            for (int j = 0; j < 4; j++) upk2(acc[j][dp], e0[j], e1[j]);
            *(float4*)&KVout[(d0 + 2 * dp) * 64 + j0] =
                make_float4(e0[0], e0[1], e0[2], e0[3]);
            *(float4*)&KVout[(d0 + 2 * dp + 1) * 64 + j0] =
                make_float4(e1[0], e1[1], e1[2], e1[3]);
        }
    }

    float* Kzout = g_kz + (h * NCHUNK + c) * DP2;
    for (int D = tid; D < DP2; D += 256) {
        float s = 0;
#pragma unroll 4
        for (int t = 0; t < 128; t++) s += phik[t * DP2 + D];
        Kzout[D] = s;
    }
}

// ---------------- ST: exclusive-prefix S -> split-bf16 B rows + z -----------
#define ST_SMEM (DP2 * 65 * 4)

__global__ __launch_bounds__(256) void st_kernel() {
    extern __shared__ __align__(16) float S[];     // [280][65]
    const int c = blockIdx.x, h = blockIdx.y;
    const int tid = threadIdx.x;

    for (int i = tid; i < DP2 * 64; i += 256) {
        const int D = i >> 6, j = i & 63;
        float s = 0.f;
        for (int cc = 0; cc < c; cc++)
            s += g_kv[((h * NCHUNK + cc) * DP2 + D) * 64 + j];
        S[D * 65 + j] = s;
    }
    for (int D = tid; D < 288; D += 256) {
        float s = 0.f;
        if (D < DFEAT)
            for (int cc = 0; cc < c; cc++)
                s += g_kz[(h * NCHUNK + cc) * DP2 + D];
        g_z[(h * NCHUNK + c) * 288 + D] = s;
    }
    __syncthreads();

    __nv_bfloat16* dst = g_st + (size_t)(h * NCHUNK + c) * 64 * KPQ;
    for (int j = 0; j < 64; j++) {
        for (int col = tid; col < KPQ; col += 256) {
            int sec = (col >= 576) ? 2 : (col >= 288 ? 1 : 0);
            int cs = col - sec * 288;
            float v = (col < 864 && cs < DFEAT) ? S[cs * 65 + j] : 0.f;
            __nv_bfloat16 hb = __float2bfloat16(v);
            __nv_bfloat16 ob = (sec == 1)
                ? __float2bfloat16(v - __bfloat162float(hb)) : hb;
            dst[j * KPQ + col] = ob;
        }
    }
}

// ---------------- SC: scores + V^T (split) + exact fp32 den -----------------
#define SC_SMEM ((2048 + 2048 + 128 * 65 + 256 + 288) * 4)

__global__ __launch_bounds__(256) void score_kernel() {
    extern __shared__ __align__(16) float smc[];
    float* qb = smc;                  // 128*16
    float* kb = qb + 2048;            // 128*16
    float* vb = kb + 2048;            // 128*65
    float* ps = vb + 128 * 65;        // 256 partial row sums
    float* zz = ps + 256;             // 288

    const int c = blockIdx.x, h = blockIdx.y;
    const int tid = threadIdx.x;
    const int rowbase = c * CHUNK;

    for (int i = tid; i < 512; i += 256) {
        int t = i >> 2, q4 = (i & 3) * 4;
        const float* base = &g_qkv[(rowbase + t) * 1536];
        *(float4*)&qb[t * 16 + q4] = *(const float4*)&base[h * 16 + q4];
        *(float4*)&kb[t * 16 + q4] = *(const float4*)&base[256 + h * 16 + q4];
    }
    for (int i = tid; i < 2048; i += 256) {
        int t = i >> 4, q4 = (i & 15) * 4;
        float4 v = *(const float4*)&g_qkv[(rowbase + t) * 1536 + 512 + h * 64 + q4];
        vb[t * 65 + q4 + 0] = v.x; vb[t * 65 + q4 + 1] = v.y;
        vb[t * 65 + q4 + 2] = v.z; vb[t * 65 + q4 + 3] = v.w;
    }
    for (int i = tid; i < 288; i += 256)
        zz[i] = g_z[(h * NCHUNK + c) * 288 + i];
    __syncthreads();

    // scores: thread = (t, half)
    {
        const int t = tid >> 1, sh = (tid & 1) * 64;
        float qv[16];
#pragma unroll
        for (int i = 0; i < 16; i += 4) {
            float4 f = *(const float4*)&qb[t * 16 + i];
            qv[i] = f.x; qv[i + 1] = f.y; qv[i + 2] = f.z; qv[i + 3] = f.w;
        }
        __nv_bfloat16* base =
            g_score + (size_t)(h * NCHUNK + c) * 128 * KIN + t * KIN;
        float rsum = 0.f;
        for (int s2 = 0; s2 < 64; s2++) {
            const int s = sh + s2;
            float dot = 0.f;
#pragma unroll
            for (int i = 0; i < 16; i += 4) {
                float4 kk = *(const float4*)&kb[s * 16 + i];
                dot += qv[i] * kk.x + qv[i + 1] * kk.y +
                       qv[i + 2] * kk.z + qv[i + 3] * kk.w;
            }
            float sd = dot * 0.25f;
            float sc = fmaf(0.5f * sd, sd, 1.0f + sd);
            if (s > t) sc = 0.f;
            rsum += sc;
            __nv_bfloat16 hb = __float2bfloat16(sc);
            __nv_bfloat16 lb = __float2bfloat16(sc - __bfloat162float(hb));
            base[s] = hb; base[128 + s] = hb; base[256 + s] = lb;
        }
        ps[tid] = rsum;
    }

    // V^T split: [j][t] with [hi|lo|hi]
    {
        __nv_bfloat16* vt = g_vt + (size_t)(h * NCHUNK + c) * 64 * KIN;
        for (int i = tid; i < 8192; i += 256) {
            const int j = i >> 7, t = i & 127;
            float v = vb[t * 65 + j];
            __nv_bfloat16 hb = __float2bfloat16(v);
            __nv_bfloat16 lb = __float2bfloat16(v - __bfloat162float(hb));
            vt[j * KIN + t] = hb;
            vt[j * KIN + 128 + t] = lb;
            vt[j * KIN + 256 + t] = hb;
        }
    }
    __syncthreads();

    // exact fp32 denominator
    if (tid < 128) {
        const int t = tid;
        float qv[16];
#pragma unroll
        for (int i = 0; i < 16; i += 4) {
            float4 f = *(const float4*)&qb[t * 16 + i];
            qv[i] = f.x; qv[i + 1] = f.y; qv[i + 2] = f.z; qv[i + 3] = f.w;
        }
        float d = zz[0] + ps[2 * t] + ps[2 * t + 1];
#pragma unroll 4
        for (int i = 0; i < 16; i++) d = fmaf(qv[i] * PHI_C1, zz[1 + i], d);
        for (int a = 0; a < 16; a++) {
            const float qa = qv[a] * PHI_C2;
            const float* zb = &zz[17 + a * 16];
#pragma unroll 4
            for (int b = 0; b < 16; b++) d = fmaf(qa * qv[b], zb[b], d);
        }
        g_den[(h * NCHUNK + c) * 128 + t] = d;
    }
}

// ---------------- A2: HMMA attention GEMM, K=1280, divide, write y2 ---------
#define A2_NST   20          // 14 inter (K=896) + 6 intra (K=384)
#define A2_ROWS  192
#define A2_SB    (A2_ROWS * ROWB)            // 27648
#define A2_SMEM  (3 * A2_SB + 512)

__global__ __launch_bounds__(256) void attn2_kernel() {
    extern __shared__ __align__(128) char sma[];
    const uint32_t sbase = smem_u32(sma);
    float* denb = (float*)(sma + 3 * A2_SB);

    const int c = blockIdx.x, h = blockIdx.y;
    const int tid = threadIdx.x, lid = tid & 31, wid = tid >> 5;
    const int wm = wid & 1, wn = wid >> 1;       // 2m x 4n, WN=16

    if (tid < 128) denb[tid] = g_den[(h * NCHUNK + c) * 128 + tid];

    const __nv_bfloat16* Aq = g_phiq + ((size_t)h * LSEQ + c * 128) * KPQ;
    const __nv_bfloat16* Bq = g_st + (size_t)(h * NCHUNK + c) * 64 * KPQ;
    const __nv_bfloat16* Ai = g_score + (size_t)(h * NCHUNK + c) * 128 * KIN;
    const __nv_bfloat16* Bi = g_vt + (size_t)(h * NCHUNK + c) * 64 * KIN;

    auto load_stage = [&](int s, int buf) {
        const uint32_t base = sbase + buf * A2_SB;
        const __nv_bfloat16* Ab; const __nv_bfloat16* Bb;
        size_t lda, ldb;
        if (s < 14) { Ab = Aq + s * 64; Bb = Bq + s * 64; lda = KPQ; ldb = KPQ; }
        else { Ab = Ai + (s - 14) * 64; Bb = Bi + (s - 14) * 64; lda = KIN; ldb = KIN; }
#pragma unroll
        for (int i = 0; i < 6; i++) {
            int idx = tid + i * 256;
            int row = idx >> 3, ch = idx & 7;
            const __nv_bfloat16* g = (row < 128)
                ? Ab + (size_t)row * lda + ch * 8
                : Bb + (size_t)(row - 128) * ldb + ch * 8;
            cp16(base + row * ROWB + ch * 16, g);
        }
        asm volatile("cp.async.commit_group;" ::: "memory");
    };

    auto load_frags = [&](int buf, int k, uint32_t af[4][4], uint32_t bfr[2][2]) {
        const uint32_t abase = sbase + buf * A2_SB +
            (wm * 64 + (lid & 15)) * ROWB + (lid >> 4) * 16 + k * 32;
#pragma unroll
        for (int mt = 0; mt < 4; mt++)
            ldsm_x4(af[mt][0], af[mt][1], af[mt][2], af[mt][3],
                    abase + mt * 16 * ROWB);
        const uint32_t bbase = sbase + buf * A2_SB + 128 * ROWB +
            (wn * 16 + (lid & 15)) * ROWB + (lid >> 4) * 16 + k * 32;
        uint32_t r0, r1, r2, r3;
        ldsm_x4(r0, r1, r2, r3, bbase);
        bfr[0][0] = r0; bfr[0][1] = r2;
        bfr[1][0] = r1; bfr[1][1] = r3;
    };

    float acc[4][2][4] = {};

    load_stage(0, 0);
    load_stage(1, 1);

    uint32_t af[2][4][4], bfr[2][2][2];

    for (int s = 0; s < A2_NST; s++) {
        const int buf = s % 3;
        asm volatile("cp.async.wait_group 1;" ::: "memory");
        __syncthreads();
        load_frags(buf, 0, af[0], bfr[0]);
        if (s + 2 < A2_NST) load_stage(s + 2, (s + 2) % 3);
#pragma unroll
        for (int k = 0; k < 4; k++) {
            if (k < 3) load_frags(buf, k + 1, af[(k + 1) & 1], bfr[(k + 1) & 1]);
#pragma unroll
            for (int mt = 0; mt < 4; mt++)
#pragma unroll
                for (int nt = 0; nt < 2; nt++)
                    mma16816(acc[mt][nt], af[k & 1][mt], bfr[k & 1][nt]);
        }
        __syncthreads();
    }

    // epilogue: y = num/(den+eps), write split-bf16 y2 ([hi|hi|lo])
    const int r = lid >> 2, cq = (lid & 3) * 2;
#pragma unroll
    for (int mt = 0; mt < 4; mt++) {
        const int row0 = wm * 64 + mt * 16 + r;
        const float rd0 = 1.0f / (denb[row0] + EPSV);
        const float rd8 = 1.0f / (denb[row0 + 8] + EPSV);
#pragma unroll
        for (int nt = 0; nt < 2; nt++) {
            const int col = wn * 16 + nt * 8 + cq;
            float y0 = acc[mt][nt][0] * rd0, y1 = acc[mt][nt][1] * rd0;
            float y2v = acc[mt][nt][2] * rd8, y3 = acc[mt][nt][3] * rd8;

            __nv_bfloat162 h0 = __floats2bfloat162_rn(y0, y1);
            __nv_bfloat162 l0 = __floats2bfloat162_rn(
                y0 - __bfloat162float(h0.x), y1 - __bfloat162float(h0.y));
            __nv_bfloat162 h8 = __floats2bfloat162_rn(y2v, y3);
            __nv_bfloat162 l8 = __floats2bfloat162_rn(
                y2v - __bfloat162float(h8.x), y3 - __bfloat162float(h8.y));

            __nv_bfloat16* b0 = g_y2 + (size_t)(c * 128 + row0) * KSPLIT + h * 64 + col;
            *(__nv_bfloat162*)b0 = h0;
            *(__nv_bfloat162*)(b0 + 1024) = h0;
            *(__nv_bfloat162*)(b0 + 2048) = l0;
            __nv_bfloat16* b8 = b0 + (size_t)8 * KSPLIT;
            *(__nv_bfloat162*)b8 = h8;
            *(__nv_bfloat162*)(b8 + 1024) = h8;
            *(__nv_bfloat162*)(b8 + 2048) = l8;
        }
    }
}

// ---------------------------------------------------------------------------
#define SM128 (4 * (256 * ROWB))
#define SM64  (4 * (192 * ROWB))

extern "C" void kernel_launch(void* const* d_in, const int* in_sizes, int n_in,
                              void* d_out, int out_size) {
    (void)in_sizes; (void)n_in; (void)out_size;
    const float* hs = (const float*)d_in[0];
    const float* Wq = (const float*)d_in[1];
    const float* Wk = (const float*)d_in[2];
    const float* Wv = (const float*)d_in[3];
    const float* Wo = (const float*)d_in[4];
    float* out = (float*)d_out;

    cudaFuncSetAttribute(mma_gemm_kernel<128>,
                         cudaFuncAttributeMaxDynamicSharedMemorySize, SM128);
    cudaFuncSetAttribute(mma_gemm_kernel<64>,
                         cudaFuncAttributeMaxDynamicSharedMemorySize, SM64);
    cudaFuncSetAttribute(chunk_kv_kernel,
                         cudaFuncAttributeMaxDynamicSharedMemorySize, K2_SMEM);
    cudaFuncSetAttribute(st_kernel,
                         cudaFuncAttributeMaxDynamicSharedMemorySize, ST_SMEM);
    cudaFuncSetAttribute(score_kernel,
                         cudaFuncAttributeMaxDynamicSharedMemorySize, SC_SMEM);
    cudaFuncSetAttribute(attn2_kernel,
                         cudaFuncAttributeMaxDynamicSharedMemorySize, A2_SMEM);

    __nv_bfloat16 *hs2, *w1, *y2, *wo2;
    float* qkv;
    cudaGetSymbolAddress((void**)&hs2, g_hs2);
    cudaGetSymbolAddress((void**)&w1,  g_w1);
    cudaGetSymbolAddress((void**)&y2,  g_y2);
    cudaGetSymbolAddress((void**)&wo2, g_wo2);
    cudaGetSymbolAddress((void**)&qkv, g_qkv);

    split_all_kernel<<<3584, 256>>>(hs, Wq, Wk, Wv, Wo);
    mma_gemm_kernel<128><<<dim3(12, 8), 256, SM128>>>(hs2, w1, qkv, 1536);
    phiq_kernel<<<1024, 256>>>();
    chunk_kv_kernel<<<dim3(NCHUNK, NH), 256, K2_SMEM>>>();
    st_kernel<<<dim3(NCHUNK, NH), 256, ST_SMEM>>>();
    score_kernel<<<dim3(NCHUNK, NH), 256, SC_SMEM>>>();
    attn2_kernel<<<dim3(NCHUNK, NH), 256, A2_SMEM>>>();
    mma_gemm_kernel<64><<<dim3(16, 8), 256, SM64>>>(y2, wo2, out, 1024);
}

// round 10
// speedup vs baseline: 1.7978x; 1.7978x over previous
#include <cuda_runtime.h>
#include <cuda_bf16.h>
#include <cstdint>

// ---------------------------------------------------------------------------
// LinearAttention via polynomial flash attention.
//   phi(q).phi(k) = 1 + s + s^2/2,  s = q.k/4   (Taylor feature identity)
// so causal linear attention == causal polynomial attention:
//   y_t = sum_{s<=t} sc(t,s) v_s / sum_{s<=t} sc(t,s)
//
//   S:  split hs/W1/Wo to K-concat split-bf16 (K=3072)
//   G1: qkv = hs2 @ W1^T                (mma.sync bf16, 4-stage cp.async)
//   FA: per (tb, h): flash loop over s-blocks: QK^T HMMA (split, K=48),
//       polynomial+mask+fp32 rowsum, score@V HMMA (3 passes, K=128 each),
//       divide, write split-bf16 y2
//   G2: out = y2 @ Wo2^T
// ---------------------------------------------------------------------------

#define LSEQ   1024
#define NH     16
#define EPSV   1e-12f
#define KSPLIT 3072
#define NSTAGE 48
#define ROWB   144

// flash smem layout
#define APITCH 112                       // 48 bf16 cols + pad
#define SPITCH 272                       // 128 bf16 cols + pad
#define AQ_OFF 0
#define BK_OFF 14336
#define SH_OFF 28672
#define SL_OFF 63488
#define VH_OFF 98304
#define VL_OFF 115712
#define DEN_OFF 133120
#define FA_SMEM 135168

// Scratch (static device globals; no allocation allowed)
__device__ __align__(16) float g_qkv[LSEQ * 1536];
__device__ __align__(16) __nv_bfloat16 g_hs2[LSEQ * KSPLIT];
__device__ __align__(16) __nv_bfloat16 g_w1 [1536 * KSPLIT];
__device__ __align__(16) __nv_bfloat16 g_y2 [LSEQ * KSPLIT];
__device__ __align__(16) __nv_bfloat16 g_wo2[1024 * KSPLIT];

// ---------------- PTX helpers -----------------------------------------------
__device__ __forceinline__ uint32_t smem_u32(const void* p) {
    uint32_t a;
    asm("{ .reg .u64 t; cvta.to.shared.u64 t, %1; cvt.u32.u64 %0, t; }"
        : "=r"(a) : "l"(p));
    return a;
}
__device__ __forceinline__ void cp16(uint32_t saddr, const void* g) {
    asm volatile("cp.async.cg.shared.global [%0], [%1], 16;"
                 :: "r"(saddr), "l"(g) : "memory");
}
__device__ __forceinline__ void ldsm_x4(uint32_t& r0, uint32_t& r1,
                                        uint32_t& r2, uint32_t& r3,
                                        uint32_t addr) {
    asm volatile("ldmatrix.sync.aligned.m8n8.x4.shared.b16 {%0,%1,%2,%3}, [%4];"
                 : "=r"(r0), "=r"(r1), "=r"(r2), "=r"(r3) : "r"(addr));
}
__device__ __forceinline__ void mma16816(float* c, const uint32_t* a,
                                         const uint32_t* b) {
    asm volatile("mma.sync.aligned.m16n8k16.row.col.f32.bf16.bf16.f32 "
                 "{%0,%1,%2,%3}, {%4,%5,%6,%7}, {%8,%9}, {%0,%1,%2,%3};"
                 : "+f"(c[0]), "+f"(c[1]), "+f"(c[2]), "+f"(c[3])
                 : "r"(a[0]), "r"(a[1]), "r"(a[2]), "r"(a[3]),
                   "r"(b[0]), "r"(b[1]));
}

// ---------------- fused split kernel ----------------------------------------
__device__ __forceinline__ void split4(float4 x, __nv_bfloat162& h01,
                                       __nv_bfloat162& h23, __nv_bfloat162& l01,
                                       __nv_bfloat162& l23) {
    h01 = __floats2bfloat162_rn(x.x, x.y);
    h23 = __floats2bfloat162_rn(x.z, x.w);
    l01 = __floats2bfloat162_rn(x.x - __bfloat162float(h01.x),
                                x.y - __bfloat162float(h01.y));
    l23 = __floats2bfloat162_rn(x.z - __bfloat162float(h23.x),
                                x.w - __bfloat162float(h23.y));
}

__global__ __launch_bounds__(256) void split_all_kernel(
    const float* __restrict__ hs, const float* __restrict__ Wq,
    const float* __restrict__ Wk, const float* __restrict__ Wv,
    const float* __restrict__ Wo) {
    const int r = blockIdx.x, c = threadIdx.x * 4;
    const float* src;
    __nv_bfloat16* dst;
    bool alay;
    if (r < 1024) {
        src = hs + (size_t)r * 1024; dst = g_hs2 + (size_t)r * KSPLIT; alay = true;
    } else if (r < 2560) {
        int rr = r - 1024;
        const float* w; int wr;
        if (rr < 256)      { w = Wq; wr = rr; }
        else if (rr < 512) { w = Wk; wr = rr - 256; }
        else               { w = Wv; wr = rr - 512; }
        src = w + (size_t)wr * 1024; dst = g_w1 + (size_t)rr * KSPLIT; alay = false;
    } else {
        int rr = r - 2560;
        src = Wo + (size_t)rr * 1024; dst = g_wo2 + (size_t)rr * KSPLIT; alay = false;
    }
    float4 x = *(const float4*)&src[c];
    __nv_bfloat162 h01, h23, l01, l23;
    split4(x, h01, h23, l01, l23);
    __nv_bfloat162* d0 = (__nv_bfloat162*)&dst[c];
    __nv_bfloat162* d1 = (__nv_bfloat162*)&dst[1024 + c];
    __nv_bfloat162* d2 = (__nv_bfloat162*)&dst[2048 + c];
    d0[0] = h01; d0[1] = h23;
    if (alay) { d1[0] = h01; d1[1] = h23; d2[0] = l01; d2[1] = l23; }
    else      { d1[0] = l01; d1[1] = l23; d2[0] = h01; d2[1] = h23; }
}

// ---------------- mma.sync bf16 NT GEMM (projections) -----------------------
template <int NTILE>
__global__ __launch_bounds__(256) void mma_gemm_kernel(
    const __nv_bfloat16* __restrict__ A, const __nv_bfloat16* __restrict__ B,
    float* __restrict__ C, int ldc) {
    constexpr int WN   = NTILE / 4;
    constexpr int NT8  = WN / 8;
    constexpr int ROWS = 128 + NTILE;
    constexpr int SBYTES = ROWS * ROWB;

    extern __shared__ __align__(128) char sm[];
    const uint32_t sbase = smem_u32(sm);
    const int tid = threadIdx.x, lid = tid & 31, wid = tid >> 5;
    const int m0 = blockIdx.y * 128, n0 = blockIdx.x * NTILE;
    const int wm = wid & 1, wn = wid >> 1;

    auto load_stage = [&](int s, int buf) {
        const uint32_t base = sbase + buf * SBYTES;
#pragma unroll
        for (int i = 0; i < ROWS / 32; i++) {
            int idx = tid + i * 256;
            int row = idx >> 3, ch = idx & 7;
            const __nv_bfloat16* g =
                (row < 128)
                    ? A + (size_t)(m0 + row) * KSPLIT + s * 64 + ch * 8
                    : B + (size_t)(n0 + row - 128) * KSPLIT + s * 64 + ch * 8;
            cp16(base + row * ROWB + ch * 16, g);
        }
    };

    auto load_frags = [&](int buf, int k, uint32_t af[4][4],
                          uint32_t bfr[NT8][2]) {
        const uint32_t abase = sbase + buf * SBYTES +
            (wm * 64 + (lid & 15)) * ROWB + (lid >> 4) * 16 + k * 32;
#pragma unroll
        for (int mt = 0; mt < 4; mt++)
            ldsm_x4(af[mt][0], af[mt][1], af[mt][2], af[mt][3],
                    abase + mt * 16 * ROWB);
        const uint32_t bbase = sbase + buf * SBYTES + 128 * ROWB +
            (wn * WN + (lid & 15)) * ROWB + (lid >> 4) * 16 + k * 32;
#pragma unroll
        for (int nt2 = 0; nt2 < NT8 / 2; nt2++) {
            uint32_t r0, r1, r2, r3;
            ldsm_x4(r0, r1, r2, r3, bbase + nt2 * 16 * ROWB);
            bfr[2 * nt2][0] = r0; bfr[2 * nt2][1] = r2;
            bfr[2 * nt2 + 1][0] = r1; bfr[2 * nt2 + 1][1] = r3;
        }
    };

    float acc[4][NT8][4] = {};

    load_stage(0, 0); asm volatile("cp.async.commit_group;" ::: "memory");
    load_stage(1, 1); asm volatile("cp.async.commit_group;" ::: "memory");
    load_stage(2, 2); asm volatile("cp.async.commit_group;" ::: "memory");

    uint32_t af[2][4][4], bfr[2][NT8][2];

    for (int s = 0; s < NSTAGE; s++) {
        const int buf = s & 3;
        asm volatile("cp.async.wait_group 2;" ::: "memory");
        __syncthreads();
        load_frags(buf, 0, af[0], bfr[0]);
        if (s + 3 < NSTAGE) load_stage(s + 3, (s + 3) & 3);
        asm volatile("cp.async.commit_group;" ::: "memory");
#pragma unroll
        for (int k = 0; k < 4; k++) {
            if (k < 3) load_frags(buf, k + 1, af[(k + 1) & 1], bfr[(k + 1) & 1]);
#pragma unroll
            for (int mt = 0; mt < 4; mt++)
#pragma unroll
                for (int nt = 0; nt < NT8; nt++)
                    mma16816(acc[mt][nt], af[k & 1][mt], bfr[k & 1][nt]);
        }
    }

    const int r = lid >> 2, cq = (lid & 3) * 2;
#pragma unroll
    for (int mt = 0; mt < 4; mt++) {
        const int mrow = m0 + wm * 64 + mt * 16 + r;
#pragma unroll
        for (int nt = 0; nt < NT8; nt++) {
            const int col = n0 + wn * WN + nt * 8 + cq;
            *(float2*)&C[(size_t)mrow * ldc + col] =
                make_float2(acc[mt][nt][0], acc[mt][nt][1]);
            *(float2*)&C[(size_t)(mrow + 8) * ldc + col] =
                make_float2(acc[mt][nt][2], acc[mt][nt][3]);
        }
    }
}

// ---------------- FA: polynomial flash attention ----------------------------
__global__ __launch_bounds__(256) void flash_kernel() {
    extern __shared__ __align__(128) char sm[];
    const uint32_t sb = smem_u32(sm);
    float* denS = (float*)(sm + DEN_OFF);       // [4][128]

    const int tb = blockIdx.x, h = blockIdx.y;
    const int tid = threadIdx.x, lid = tid & 31, wid = tid >> 5;
    const int wm = wid & 1, wn = wid >> 1;
    const int r = lid >> 2, cq = (lid & 3) * 2;

    for (int i = tid; i < 512; i += 256) denS[i] = 0.f;

    // build Aq: q split [hi|hi|lo], K=48
    for (int i = tid; i < 2048; i += 256) {
        int t = i >> 4, ii = i & 15;
        float q = g_qkv[(tb * 128 + t) * 1536 + h * 16 + ii];
        __nv_bfloat16 hq = __float2bfloat16(q);
        __nv_bfloat16 lq = __float2bfloat16(q - __bfloat162float(hq));
        __nv_bfloat16* row = (__nv_bfloat16*)(sm + AQ_OFF + t * APITCH);
        row[ii] = hq; row[16 + ii] = hq; row[32 + ii] = lq;
    }

    float acc_o[4][2][4] = {};

    for (int sblk = 0; sblk <= tb; sblk++) {
        __syncthreads();   // previous iteration's smem reads done

        // build Bk: k split [hi|lo|hi]
        for (int i = tid; i < 2048; i += 256) {
            int s = i >> 4, ii = i & 15;
            float k = g_qkv[(sblk * 128 + s) * 1536 + 256 + h * 16 + ii];
            __nv_bfloat16 hk = __float2bfloat16(k);
            __nv_bfloat16 lk = __float2bfloat16(k - __bfloat162float(hk));
            __nv_bfloat16* row = (__nv_bfloat16*)(sm + BK_OFF + s * APITCH);
            row[ii] = hk; row[16 + ii] = lk; row[32 + ii] = hk;
        }
        // build Vh/Vl transposed: [j][s]
        for (int i = tid; i < 8192; i += 256) {
            int s = i >> 6, j = i & 63;
            float v = g_qkv[(sblk * 128 + s) * 1536 + 512 + h * 64 + j];
            __nv_bfloat16 hv = __float2bfloat16(v);
            __nv_bfloat16 lv = __float2bfloat16(v - __bfloat162float(hv));
            ((__nv_bfloat16*)(sm + VH_OFF + j * SPITCH))[s] = hv;
            ((__nv_bfloat16*)(sm + VL_OFF + j * SPITCH))[s] = lv;
        }
        __syncthreads();

        // QK^T: 128x128, K=48 split
        float acc_s[4][4][4] = {};
#pragma unroll
        for (int k = 0; k < 3; k++) {
            uint32_t af[4][4], bf[4][2];
            const uint32_t abase = sb + AQ_OFF +
                (wm * 64 + (lid & 15)) * APITCH + (lid >> 4) * 16 + k * 32;
#pragma unroll
            for (int mt = 0; mt < 4; mt++)
                ldsm_x4(af[mt][0], af[mt][1], af[mt][2], af[mt][3],
                        abase + mt * 16 * APITCH);
            const uint32_t bbase = sb + BK_OFF +
                (wn * 32 + (lid & 15)) * APITCH + (lid >> 4) * 16 + k * 32;
#pragma unroll
            for (int nt2 = 0; nt2 < 2; nt2++) {
                uint32_t r0, r1, r2, r3;
                ldsm_x4(r0, r1, r2, r3, bbase + nt2 * 16 * APITCH);
                bf[2 * nt2][0] = r0; bf[2 * nt2][1] = r2;
                bf[2 * nt2 + 1][0] = r1; bf[2 * nt2 + 1][1] = r3;
            }
#pragma unroll
            for (int mt = 0; mt < 4; mt++)
#pragma unroll
                for (int nt = 0; nt < 4; nt++)
                    mma16816(acc_s[mt][nt], af[mt], bf[nt]);
        }

        // polynomial + mask + den rowsum + split store
        const bool diag = (sblk == tb);
#pragma unroll
        for (int mt = 0; mt < 4; mt++) {
            const int tr0 = wm * 64 + mt * 16 + r;
            const int tr8 = tr0 + 8;
            float d0 = 0.f, d8 = 0.f;
#pragma unroll
            for (int nt = 0; nt < 4; nt++) {
                const int cl = wn * 32 + nt * 8 + cq;
                float* c = acc_s[mt][nt];
                float sc[4];
#pragma unroll
                for (int e = 0; e < 4; e++) {
                    float sd = c[e] * 0.25f;
                    sc[e] = fmaf(0.5f * sd, sd, 1.0f + sd);
                }
                if (diag) {
                    if (cl > tr0) sc[0] = 0.f;
                    if (cl + 1 > tr0) sc[1] = 0.f;
                    if (cl > tr8) sc[2] = 0.f;
                    if (cl + 1 > tr8) sc[3] = 0.f;
                }
                d0 += sc[0] + sc[1];
                d8 += sc[2] + sc[3];
                __nv_bfloat162 h0 = __floats2bfloat162_rn(sc[0], sc[1]);
                __nv_bfloat162 l0 = __floats2bfloat162_rn(
                    sc[0] - __bfloat162float(h0.x), sc[1] - __bfloat162float(h0.y));
                __nv_bfloat162 h8 = __floats2bfloat162_rn(sc[2], sc[3]);
                __nv_bfloat162 l8 = __floats2bfloat162_rn(
                    sc[2] - __bfloat162float(h8.x), sc[3] - __bfloat162float(h8.y));
                *(__nv_bfloat162*)(sm + SH_OFF + tr0 * SPITCH + cl * 2) = h0;
                *(__nv_bfloat162*)(sm + SL_OFF + tr0 * SPITCH + cl * 2) = l0;
                *(__nv_bfloat162*)(sm + SH_OFF + tr8 * SPITCH + cl * 2) = h8;
                *(__nv_bfloat162*)(sm + SL_OFF + tr8 * SPITCH + cl * 2) = l8;
            }
            // reduce within lane-quad (same row)
            d0 += __shfl_xor_sync(0xFFFFFFFF, d0, 1);
            d0 += __shfl_xor_sync(0xFFFFFFFF, d0, 2);
            d8 += __shfl_xor_sync(0xFFFFFFFF, d8, 1);
            d8 += __shfl_xor_sync(0xFFFFFFFF, d8, 2);
            if ((lid & 3) == 0) {
                denS[wn * 128 + tr0] += d0;
                denS[wn * 128 + tr8] += d8;
            }
        }
        __syncthreads();

        // O += Sh@Vh^T + Sh@Vl^T + Sl@Vh^T  (each K=128)
#pragma unroll
        for (int p = 0; p < 3; p++) {
            const uint32_t Ab = sb + (p == 2 ? SL_OFF : SH_OFF);
            const uint32_t Bb = sb + (p == 1 ? VL_OFF : VH_OFF);
#pragma unroll
            for (int k8 = 0; k8 < 8; k8++) {
                uint32_t af[4][4], bf[2][2];
                const uint32_t abase = Ab +
                    (wm * 64 + (lid & 15)) * SPITCH + (lid >> 4) * 16 + k8 * 32;
#pragma unroll
                for (int mt = 0; mt < 4; mt++)
                    ldsm_x4(af[mt][0], af[mt][1], af[mt][2], af[mt][3],
                            abase + mt * 16 * SPITCH);
                const uint32_t bbase = Bb +
                    (wn * 16 + (lid & 15)) * SPITCH + (lid >> 4) * 16 + k8 * 32;
                uint32_t r0, r1, r2, r3;
                ldsm_x4(r0, r1, r2, r3, bbase);
                bf[0][0] = r0; bf[0][1] = r2;
                bf[1][0] = r1; bf[1][1] = r3;
#pragma unroll
                for (int mt = 0; mt < 4; mt++)
#pragma unroll
                    for (int nt = 0; nt < 2; nt++)
                        mma16816(acc_o[mt][nt], af[mt], bf[nt]);
            }
        }
    }
    __syncthreads();

    // epilogue: y = O/den, write split-bf16 y2 ([hi|hi|lo])
#pragma unroll
    for (int mt = 0; mt < 4; mt++) {
        const int row0 = wm * 64 + mt * 16 + r;
        const int row8 = row0 + 8;
        const float den0 = denS[row0] + denS[128 + row0] +
                           denS[256 + row0] + denS[384 + row0] + EPSV;
        const float den8 = denS[row8] + denS[128 + row8] +
                           denS[256 + row8] + denS[384 + row8] + EPSV;
        const float rd0 = 1.0f / den0, rd8 = 1.0f / den8;
#pragma unroll
        for (int nt = 0; nt < 2; nt++) {
            const int col = wn * 16 + nt * 8 + cq;
            float y0 = acc_o[mt][nt][0] * rd0, y1 = acc_o[mt][nt][1] * rd0;
            float y2v = acc_o[mt][nt][2] * rd8, y3 = acc_o[mt][nt][3] * rd8;

            __nv_bfloat162 h0 = __floats2bfloat162_rn(y0, y1);
            __nv_bfloat162 l0 = __floats2bfloat162_rn(
                y0 - __bfloat162float(h0.x), y1 - __bfloat162float(h0.y));
            __nv_bfloat162 h8 = __floats2bfloat162_rn(y2v, y3);
            __nv_bfloat162 l8 = __floats2bfloat162_rn(
                y2v - __bfloat162float(h8.x), y3 - __bfloat162float(h8.y));

            __nv_bfloat16* b0 =
                g_y2 + (size_t)(tb * 128 + row0) * KSPLIT + h * 64 + col;
            *(__nv_bfloat162*)b0 = h0;
            *(__nv_bfloat162*)(b0 + 1024) = h0;
            *(__nv_bfloat162*)(b0 + 2048) = l0;
            __nv_bfloat16* b8 = b0 + (size_t)8 * KSPLIT;
            *(__nv_bfloat162*)b8 = h8;
            *(__nv_bfloat162*)(b8 + 1024) = h8;
            *(__nv_bfloat162*)(b8 + 2048) = l8;
        }
    }
}

// ---------------------------------------------------------------------------
#define SM128 (4 * (256 * ROWB))
#define SM64  (4 * (192 * ROWB))

extern "C" void kernel_launch(void* const* d_in, const int* in_sizes, int n_in,
                              void* d_out, int out_size) {
    (void)in_sizes; (void)n_in; (void)out_size;
    const float* hs = (const float*)d_in[0];
    const float* Wq = (const float*)d_in[1];
    const float* Wk = (const float*)d_in[2];
    const float* Wv = (const float*)d_in[3];
    const float* Wo = (const float*)d_in[4];
    float* out = (float*)d_out;

    cudaFuncSetAttribute(mma_gemm_kernel<128>,
                         cudaFuncAttributeMaxDynamicSharedMemorySize, SM128);
    cudaFuncSetAttribute(mma_gemm_kernel<64>,
                         cudaFuncAttributeMaxDynamicSharedMemorySize, SM64);
    cudaFuncSetAttribute(flash_kernel,
                         cudaFuncAttributeMaxDynamicSharedMemorySize, FA_SMEM);

    __nv_bfloat16 *hs2, *w1, *y2, *wo2;
    float* qkv;
    cudaGetSymbolAddress((void**)&hs2, g_hs2);
    cudaGetSymbolAddress((void**)&w1,  g_w1);
    cudaGetSymbolAddress((void**)&y2,  g_y2);
    cudaGetSymbolAddress((void**)&wo2, g_wo2);
    cudaGetSymbolAddress((void**)&qkv, g_qkv);

    split_all_kernel<<<3584, 256>>>(hs, Wq, Wk, Wv, Wo);
    mma_gemm_kernel<128><<<dim3(12, 8), 256, SM128>>>(hs2, w1, qkv, 1536);
    flash_kernel<<<dim3(8, NH), 256, FA_SMEM>>>();
    mma_gemm_kernel<64><<<dim3(16, 8), 256, SM64>>>(y2, wo2, out, 1024);
}